// round 15
// baseline (speedup 1.0000x reference)
#include <cuda_runtime.h>
#include <math.h>

#define NCLS 40
#define QN 100
#define BN 4
#define HW 65536
#define THREADS 256
#define NWARP (THREADS/32)
#define PPT 4
#define PIX (THREADS*PPT)          // 1024 pixels per block
#define WPIX 128                   // pixels per warp
#define NC1 (NCLS+1)
#define QG 4                       // q-groups
#define QPG (QN/QG)                // 25 queries per group
#define NPIX (BN*HW)               // 262144 pixels
#define PIXBLK (HW/PIX)            // 64 pixel-blocks per image
#define NBLK_MAIN (QG*BN*PIXBLK)   // 1024
#define FIN_WARPS (BN*QN)          // 400
#define FIN_BLOCKS 100             // 4 warps per block

// ---- scratch (device globals; no allocation allowed) ----
__device__ float g_inter[BN*QN*NCLS];
__device__ float g_src[BN*QN];
__device__ int   g_counts[BN*QN*NCLS];
__device__ int   g_tsum[BN*NCLS];
__device__ float g_ce_sum;
__device__ int   g_nvalid;
__device__ float g_ce2, g_dice2;
__device__ int   g_done;
// per-pixel per-group partials (~13.6 MB)
__device__ float4 g_pssum[QG][NPIX/4];
__device__ float4 g_pmax [QG][NPIX/4];
__device__ float4 g_pxt  [QG][NPIX/4];
__device__ uchar4 g_pamax[QG][NPIX/4];

__global__ void zero_k() {
    int i = blockIdx.x * blockDim.x + threadIdx.x;
    if (i < BN*QN*NCLS) { g_inter[i] = 0.f; g_counts[i] = 0; }
    if (i < BN*QN) g_src[i] = 0.f;
    if (i < BN*NCLS) g_tsum[i] = 0;
    if (i == 0) { g_ce_sum = 0.f; g_nvalid = 0; g_ce2 = 0.f; g_dice2 = 0.f; g_done = 0; }
}

// Streaming pass: block = (q-group, image, 1024 pixels), 8 independent warps.
// Warp-local counting sort + staging; NO atomics in the q-loop: each lane OWNS
// classes (lane, lane+32) and serially sums its contiguous sorted segment into
// a warp-private inter row (plain smem read-modify-write).
__global__ __launch_bounds__(THREADS) void main_k(
    const float* __restrict__ masks, const int* __restrict__ targets)
{
    __shared__ __align__(16) float sig_sh[2][NWARP][WPIX];  // 8 KB double buffer
    __shared__ float interw[NWARP][QPG*NC1];                // 32.8 KB warp-private
    __shared__ int wcnt[NWARP][NC1];
    __shared__ int wbase[NWARP][NC1];
    __shared__ int wcur[NWARP][NC1];
    __shared__ float src_sh[QPG];

    const int tid  = threadIdx.x;
    const int lane = tid & 31;
    const int w    = tid >> 5;
    const int g    = blockIdx.x / (BN*PIXBLK);
    const int rem  = blockIdx.x % (BN*PIXBLK);
    const int img  = rem / PIXBLK;
    const int blk  = rem % PIXBLK;
    const int q0   = g*QPG;
    const int pixbase = img*HW + blk*PIX;

    for (int i = tid; i < NWARP*QPG*NC1; i += THREADS) ((float*)interw)[i] = 0.f;
    for (int i = lane; i < NC1; i += 32) wcnt[w][i] = 0;
    for (int i = tid; i < QPG; i += THREADS) src_sh[i] = 0.f;
    __syncthreads();   // only block barrier before the loop

    // ---- classes (4 contiguous pixels/lane) + WARP-LOCAL counting sort ----
    int myc[PPT], mypos[PPT];
    {
        int4 t4 = reinterpret_cast<const int4*>(targets + pixbase)[w*32 + lane];
        int tt[PPT] = {t4.x, t4.y, t4.z, t4.w};
        #pragma unroll
        for (int j = 0; j < PPT; j++) {
            myc[j] = ((unsigned)tt[j] < (unsigned)NCLS) ? tt[j] : NCLS; // 40 == ignore
            atomicAdd(&wcnt[w][myc[j]], 1);
        }
    }
    __syncwarp();
    if (lane == 0) {
        int r = 0;
        for (int c = 0; c < NC1; c++) { wbase[w][c] = r; r += wcnt[w][c]; }
    }
    __syncwarp();
    for (int i = lane; i < NC1; i += 32) wcur[w][i] = wbase[w][i];
    __syncwarp();
    #pragma unroll
    for (int j = 0; j < PPT; j++)
        mypos[j] = atomicAdd(&wcur[w][myc[j]], 1);
    __syncwarp();

    // lane-owned classes: lane and lane+32 (lanes 0..8 own a second class)
    const int cls0 = lane;
    const int n0 = wcnt[w][cls0];
    const int b0 = wbase[w][cls0];
    const int cls1 = lane + 32;
    int n1 = 0, b1 = 0;
    if (cls1 < NC1) { n1 = wcnt[w][cls1]; b1 = wbase[w][cls1]; }

    float ssum[PPT], mmax[PPT], xt[PPT];
    int amax[PPT];
    #pragma unroll
    for (int j = 0; j < PPT; j++) { ssum[j] = 0.f; mmax[j] = -1e30f; xt[j] = 0.f; amax[j] = q0; }

    const float4* base4 = reinterpret_cast<const float4*>(
        masks + (size_t)img*QN*HW + (size_t)blk*PIX);
    const int stride4 = HW/4;
    const int myf4 = w*32 + lane;

    float4 cur = base4[(size_t)q0*stride4 + myf4];    // prefetch first q
    for (int qi = 0; qi < QPG; qi++) {
        const int q = q0 + qi;
        float4 nxt;
        if (qi + 1 < QPG) nxt = base4[(size_t)(q+1)*stride4 + myf4];
        else nxt = make_float4(0.f, 0.f, 0.f, 0.f);

        float xv[PPT] = {cur.x, cur.y, cur.z, cur.w};
        float* sbuf = sig_sh[qi & 1][w];
        #pragma unroll
        for (int j = 0; j < PPT; j++) {
            float x = xv[j];
            if (x > mmax[j]) { mmax[j] = x; amax[j] = q; }
            xt[j] = (q == myc[j]) ? x : xt[j];
            float t = __expf(x);               // one exp serves both lse and sigmoid
            ssum[j] += t;
            sbuf[mypos[j]] = __fdividef(t, 1.f + t);  // sigmoid -> sorted slot
        }
        __syncwarp();                          // warp-local scatter->gather
        // ownership commit: lane sums its class segment(s); NO atomics
        float* iw = &interw[w][qi*NC1];
        if (n0) {
            float sa = 0.f, sb = 0.f;
            int i = 0;
            for (; i + 1 < n0; i += 2) { sa += sbuf[b0+i]; sb += sbuf[b0+i+1]; }
            if (i < n0) sa += sbuf[b0+i];
            iw[cls0] += sa + sb;               // lane owns (w, cls0)
        }
        if (n1) {
            float sa = 0.f, sb = 0.f;
            int i = 0;
            for (; i + 1 < n1; i += 2) { sa += sbuf[b1+i]; sb += sbuf[b1+i+1]; }
            if (i < n1) sa += sbuf[b1+i];
            iw[cls1] += sa + sb;               // lane owns (w, cls1)
        }
        cur = nxt;
        // no barrier: double buffer; next q's syncwarp orders buffer reuse
    }

    // ---- write per-pixel partials for combine_k ----
    {
        const int p4 = pixbase/4 + myf4;
        g_pssum[g][p4] = make_float4(ssum[0], ssum[1], ssum[2], ssum[3]);
        g_pmax [g][p4] = make_float4(mmax[0], mmax[1], mmax[2], mmax[3]);
        g_pxt  [g][p4] = make_float4(xt[0], xt[1], xt[2], xt[3]);
        g_pamax[g][p4] = make_uchar4((unsigned char)amax[0], (unsigned char)amax[1],
                                     (unsigned char)amax[2], (unsigned char)amax[3]);
    }
    __syncthreads();   // orders all interw writes before flush

    // ---- flush: sum 8 warp copies -> global inter + src ----
    for (int idx = tid; idx < QPG*NC1; idx += THREADS) {
        const int qi = idx / NC1;
        const int c  = idx - qi*NC1;
        float v = 0.f;
        #pragma unroll
        for (int ww = 0; ww < NWARP; ww++) v += interw[ww][idx];
        if (c < NCLS) atomicAdd(&g_inter[(img*QN + q0 + qi)*NCLS + c], v);
        atomicAdd(&src_sh[qi], v);     // src_sum includes ignore bin (c==40)
    }
    __syncthreads();
    for (int qi = tid; qi < QPG; qi += THREADS)
        atomicAdd(&g_src[img*QN + q0 + qi], src_sh[qi]);
}

// Cross-group combine: per-pixel ce_mask numerator, n_valid, assignment counts,
// and the per-image class histogram (== tsum, since Sum_q counts is q-free).
__global__ __launch_bounds__(THREADS) void combine_k(const int* __restrict__ targets)
{
    __shared__ float s_ce[NWARP];
    __shared__ float s_nv[NWARP];
    __shared__ int hist[NCLS];
    const int tid = threadIdx.x;
    const int lane = tid & 31;
    const int wid = tid >> 5;
    const int j = blockIdx.x * THREADS + tid;      // float4 pixel group
    const int img = (int)(((size_t)blockIdx.x * THREADS * 4) >> 16);

    for (int i = tid; i < NCLS; i += THREADS) hist[i] = 0;
    __syncthreads();

    float4 ssum = g_pssum[0][j];
    float4 mmax = g_pmax [0][j];
    float4 xt   = g_pxt  [0][j];
    uchar4 am   = g_pamax[0][j];
    #pragma unroll
    for (int g = 1; g < QG; g++) {
        float4 s2 = g_pssum[g][j];
        float4 m2 = g_pmax [g][j];
        float4 x2 = g_pxt  [g][j];
        uchar4 a2 = g_pamax[g][j];
        ssum.x += s2.x; ssum.y += s2.y; ssum.z += s2.z; ssum.w += s2.w;
        xt.x += x2.x; xt.y += x2.y; xt.z += x2.z; xt.w += x2.w;
        if (m2.x > mmax.x) { mmax.x = m2.x; am.x = a2.x; }
        if (m2.y > mmax.y) { mmax.y = m2.y; am.y = a2.y; }
        if (m2.z > mmax.z) { mmax.z = m2.z; am.z = a2.z; }
        if (m2.w > mmax.w) { mmax.w = m2.w; am.w = a2.w; }
    }
    int4 t4 = reinterpret_cast<const int4*>(targets)[j];

    float ce_l = 0.f, nv = 0.f;
    int tt[PPT] = {t4.x, t4.y, t4.z, t4.w};
    float ssv[PPT] = {ssum.x, ssum.y, ssum.z, ssum.w};
    float xtv[PPT] = {xt.x, xt.y, xt.z, xt.w};
    int amv[PPT] = {am.x, am.y, am.z, am.w};
    #pragma unroll
    for (int k = 0; k < PPT; k++) {
        if ((unsigned)tt[k] < (unsigned)NCLS) {
            ce_l += __logf(ssv[k]) - xtv[k];       // lse - x[target]
            nv += 1.f;
            atomicAdd(&hist[tt[k]], 1);
            atomicAdd(&g_counts[(img*QN + amv[k])*NCLS + tt[k]], 1);
        }
    }
    #pragma unroll
    for (int o = 16; o > 0; o >>= 1) {
        ce_l += __shfl_xor_sync(0xffffffffu, ce_l, o);
        nv   += __shfl_xor_sync(0xffffffffu, nv, o);
    }
    if (lane == 0) { s_ce[wid] = ce_l; s_nv[wid] = nv; }
    __syncthreads();
    if (wid == 0) {
        float c = (lane < NWARP) ? s_ce[lane] : 0.f;
        float n = (lane < NWARP) ? s_nv[lane] : 0.f;
        #pragma unroll
        for (int o = 4; o > 0; o >>= 1) {
            c += __shfl_xor_sync(0xffffffffu, c, o);
            n += __shfl_xor_sync(0xffffffffu, n, o);
        }
        if (lane == 0) { atomicAdd(&g_ce_sum, c); atomicAdd(&g_nvalid, (int)n); }
    }
    for (int c = tid; c < NCLS; c += THREADS)
        if (hist[c]) atomicAdd(&g_tsum[img*NCLS + c], hist[c]);
}

// Warp-per-(b,q) final reduction: lane-parallel mode/CE/dice; last warp finalizes.
__global__ __launch_bounds__(128) void fin_k(const float* __restrict__ logits,
                                             float* __restrict__ out)
{
    const int tid  = threadIdx.x;
    const int lane = tid & 31;
    const int item = blockIdx.x * 4 + (tid >> 5);   // (b,q), < 400
    const int b = item / QN;

    // ---- mode label: packed-key warp max; key = (count<<16)|(NCLS-c) ----
    const int* cp = &g_counts[item*NCLS];
    int c1 = lane, c2 = lane + 32;
    int v1 = __ldg(cp + c1);
    int v2 = (c2 < NCLS) ? __ldg(cp + c2) : 0;
    long long kk1 = ((long long)v1 << 16) | (NCLS - c1);
    long long kk2 = (c2 < NCLS) ? (((long long)v2 << 16) | (NCLS - c2)) : 0;
    long long key = kk1 > kk2 ? kk1 : kk2;
    #pragma unroll
    for (int o = 16; o > 0; o >>= 1) {
        long long other = __shfl_xor_sync(0xffffffff, key, o);
        if (other > key) key = other;
    }
    int bestcnt = (int)(key >> 16);
    int bestc = NCLS - (int)(key & 0xffff);

    // ---- focal CE over 41 logits (warp softmax) ----
    float ce_term = 0.f;
    if (bestcnt > 0) {
        const float* lg = logits + item*NC1;
        float a = __ldg(lg + lane);
        float bb = (lane < NC1 - 32) ? __ldg(lg + lane + 32) : -1e30f;
        float m = fmaxf(a, bb);
        #pragma unroll
        for (int o = 16; o > 0; o >>= 1) m = fmaxf(m, __shfl_xor_sync(0xffffffff, m, o));
        float s = __expf(a - m) + ((lane < NC1 - 32) ? __expf(bb - m) : 0.f);
        #pragma unroll
        for (int o = 16; o > 0; o >>= 1) s += __shfl_xor_sync(0xffffffff, s, o);
        float lgb = __shfl_sync(0xffffffff, (bestc < 32) ? a : bb, bestc & 31);
        float nll = m + __logf(s) - lgb;
        float p = __expf(-nll);
        float om = 1.f - p;
        ce_term = om * om * nll;
    }

    // ---- dice terms: lanes cover classes lane, lane+32 ----
    float ss = __ldg(&g_src[item]);
    float dice_l = 0.f;
    {
        float t0 = (float)__ldg(&g_tsum[0*NCLS + c1]);
        float t1 = (float)__ldg(&g_tsum[1*NCLS + c1]);
        float t2 = (float)__ldg(&g_tsum[2*NCLS + c1]);
        float t3 = (float)__ldg(&g_tsum[3*NCLS + c1]);
        float pres = (t0 + t1 + t2 + t3 > 0.f) ? 1.f : 0.f;
        float tb = (b == 0) ? t0 : (b == 1) ? t1 : (b == 2) ? t2 : t3;
        dice_l += pres * 2.f * __ldg(&g_inter[item*NCLS + c1]) / (ss + tb + 1e-8f);
        if (c2 < NCLS) {
            float u0 = (float)__ldg(&g_tsum[0*NCLS + c2]);
            float u1 = (float)__ldg(&g_tsum[1*NCLS + c2]);
            float u2 = (float)__ldg(&g_tsum[2*NCLS + c2]);
            float u3 = (float)__ldg(&g_tsum[3*NCLS + c2]);
            float pres2 = (u0 + u1 + u2 + u3 > 0.f) ? 1.f : 0.f;
            float ub = (b == 0) ? u0 : (b == 1) ? u1 : (b == 2) ? u2 : u3;
            dice_l += pres2 * 2.f * __ldg(&g_inter[item*NCLS + c2]) / (ss + ub + 1e-8f);
        }
    }
    #pragma unroll
    for (int o = 16; o > 0; o >>= 1) dice_l += __shfl_xor_sync(0xffffffff, dice_l, o);

    bool last = false;
    if (lane == 0) {
        atomicAdd(&g_ce2, ce_term);
        atomicAdd(&g_dice2, dice_l);
        __threadfence();
        last = (atomicAdd(&g_done, 1) == FIN_WARPS - 1);
    }
    if (__shfl_sync(0xffffffff, last ? 1 : 0, 0)) {
        float pr = 0.f;
        if (lane < NCLS) {
            int t = __ldg(&g_tsum[0*NCLS + lane]) + __ldg(&g_tsum[1*NCLS + lane])
                  + __ldg(&g_tsum[2*NCLS + lane]) + __ldg(&g_tsum[3*NCLS + lane]);
            pr = (t > 0) ? 1.f : 0.f;
        }
        float pr2 = 0.f;
        if (lane + 32 < NCLS) {
            int t = __ldg(&g_tsum[0*NCLS + lane+32]) + __ldg(&g_tsum[1*NCLS + lane+32])
                  + __ldg(&g_tsum[2*NCLS + lane+32]) + __ldg(&g_tsum[3*NCLS + lane+32]);
            pr2 = (t > 0) ? 1.f : 0.f;
        }
        float npres = pr + pr2;
        #pragma unroll
        for (int o = 16; o > 0; o >>= 1) npres += __shfl_xor_sync(0xffffffff, npres, o);
        if (lane == 0) {
            float ce_tot   = *(volatile float*)&g_ce2;
            float dice_tot = *(volatile float*)&g_dice2;
            float loss_ce = ce_tot / (float)(BN*QN);
            float ce_mask = g_ce_sum / fmaxf((float)g_nvalid, 1.f);
            float dice_loss = (npres - dice_tot / (float)(BN*QN)) / (float)NCLS;
            out[0] = 2.f*loss_ce + 5.f*ce_mask + 5.f*dice_loss;
        }
    }
}

extern "C" void kernel_launch(void* const* d_in, const int* in_sizes, int n_in,
                              void* d_out, int out_size)
{
    const float* logits  = (const float*)d_in[0];   // [4,100,41] f32
    const float* masks   = (const float*)d_in[1];   // [4,100,256,256] f32
    const int*   targets = (const int*)d_in[2];     // [4,256,256] i32
    float* out = (float*)d_out;

    zero_k<<<(BN*QN*NCLS + 255)/256, 256>>>();
    main_k<<<NBLK_MAIN, THREADS>>>(masks, targets);
    combine_k<<<NPIX/4/THREADS, THREADS>>>(targets);
    fin_k<<<FIN_BLOCKS, 128>>>(logits, out);
}

// round 16
// speedup vs baseline: 1.1239x; 1.1239x over previous
#include <cuda_runtime.h>
#include <math.h>

#define NCLS 40
#define QN 100
#define BN 4
#define HW 65536
#define THREADS 256
#define NWARP (THREADS/32)
#define PPT 4
#define PIX (THREADS*PPT)          // 1024 pixels per block
#define WPIX 128                   // pixels per warp
#define NC1 (NCLS+1)
#define QG 4                       // q-groups
#define QPG (QN/QG)                // 25 queries per group
#define NPIX (BN*HW)               // 262144 pixels
#define PIXBLK (HW/PIX)            // 64 pixel-blocks per image
#define NBLK_MAIN (QG*BN*PIXBLK)   // 1024
#define FIN_WARPS (BN*QN)          // 400
#define FIN_BLOCKS 100
#define FULL 0xffffffffu

// ---- scratch (device globals; no allocation allowed) ----
__device__ float g_inter[BN*QN*NCLS];
__device__ float g_src[BN*QN];
__device__ int   g_counts[BN*QN*NCLS];
__device__ int   g_tsum[BN*NCLS];
__device__ float g_ce_sum;
__device__ int   g_nvalid;
__device__ float g_ce2, g_dice2;
__device__ int   g_done;
// per-pixel per-group partials (~13.6 MB)
__device__ float4 g_pssum[QG][NPIX/4];
__device__ float4 g_pmax [QG][NPIX/4];
__device__ float4 g_pxt  [QG][NPIX/4];
__device__ uchar4 g_pamax[QG][NPIX/4];

__global__ void zero_k() {
    int i = blockIdx.x * blockDim.x + threadIdx.x;
    if (i < BN*QN*NCLS) { g_inter[i] = 0.f; g_counts[i] = 0; }
    if (i < BN*QN) g_src[i] = 0.f;
    if (i < BN*NCLS) g_tsum[i] = 0;
    if (i == 0) { g_ce_sum = 0.f; g_nvalid = 0; g_ce2 = 0.f; g_dice2 = 0.f; g_done = 0; }
}

// Streaming pass: block = (q-group, image, 1024 pixels), 8 independent warps.
// Warp-local counting sort + staging. Commit = FIXED-COST warp segmented scan
// (all class-structure flags precomputed, loop-invariant) + plain single-writer
// RMW into warp-private inter rows. ZERO atomics, zero data-dependent loops.
__global__ __launch_bounds__(THREADS) void main_k(
    const float* __restrict__ masks, const int* __restrict__ targets)
{
    __shared__ __align__(16) float sig_sh[2][NWARP][WPIX];  // 8 KB double buffer
    __shared__ float interw[NWARP][QPG*NC1];                // 32.8 KB warp-private
    __shared__ int wcnt[NWARP][NC1];
    __shared__ int wbase[NWARP][NC1];
    __shared__ int wcur[NWARP][NC1];
    __shared__ unsigned char cls_sorted[NWARP][WPIX];
    __shared__ float src_sh[QPG];

    const int tid  = threadIdx.x;
    const int lane = tid & 31;
    const int w    = tid >> 5;
    const int g    = blockIdx.x / (BN*PIXBLK);
    const int rem  = blockIdx.x % (BN*PIXBLK);
    const int img  = rem / PIXBLK;
    const int blk  = rem % PIXBLK;
    const int q0   = g*QPG;
    const int pixbase = img*HW + blk*PIX;

    for (int i = tid; i < NWARP*QPG*NC1/4; i += THREADS)
        reinterpret_cast<float4*>(interw)[i] = make_float4(0.f,0.f,0.f,0.f);
    if (tid < NWARP*QPG*NC1 - (NWARP*QPG*NC1/4)*4)   // tail (8200 % 4 == 0, no-op)
        ;
    for (int i = lane; i < NC1; i += 32) wcnt[w][i] = 0;
    for (int i = tid; i < QPG; i += THREADS) src_sh[i] = 0.f;
    __syncthreads();

    // ---- classes (4 contiguous pixels/lane) + WARP-LOCAL counting sort ----
    int myc[PPT], mypos[PPT];
    {
        int4 t4 = reinterpret_cast<const int4*>(targets + pixbase)[w*32 + lane];
        int tt[PPT] = {t4.x, t4.y, t4.z, t4.w};
        #pragma unroll
        for (int j = 0; j < PPT; j++) {
            myc[j] = ((unsigned)tt[j] < (unsigned)NCLS) ? tt[j] : NCLS; // 40 == ignore
            atomicAdd(&wcnt[w][myc[j]], 1);
        }
    }
    __syncwarp();
    if (lane == 0) {
        int r = 0;
        for (int c = 0; c < NC1; c++) { wbase[w][c] = r; r += wcnt[w][c]; }
    }
    __syncwarp();
    for (int i = lane; i < NC1; i += 32) wcur[w][i] = wbase[w][i];
    __syncwarp();
    #pragma unroll
    for (int j = 0; j < PPT; j++) {
        mypos[j] = atomicAdd(&wcur[w][myc[j]], 1);
        cls_sorted[w][mypos[j]] = (unsigned char)myc[j];
    }
    __syncwarp();
    const int k0 = (int)cls_sorted[w][lane*PPT + 0];
    const int k1 = (int)cls_sorted[w][lane*PPT + 1];
    const int k2 = (int)cls_sorted[w][lane*PPT + 2];
    const int k3 = (int)cls_sorted[w][lane*PPT + 3];

    // ---- loop-invariant segmented-scan structure ----
    const int k3p = __shfl_up_sync(FULL, k3, 1);     // k3 of lane-1
    const int k0n = __shfl_down_sync(FULL, k0, 1);   // k0 of lane+1
    const bool pass = (k0 == k3);                    // whole lane one class
    const bool conn = (lane > 0) && (k0 == k3p);     // run continues from prev lane
    const bool gg   = pass && conn;                  // chain link gate
    const bool term = (lane == 31) || (k3 != k0n);   // trail run ends here
    const bool e10 = (k1==k0), e20 = (k2==k0), e30 = (k3==k0);
    const bool e13 = (k1==k3), e23 = (k2==k3), e21 = (k2==k1);
    const bool m1 = (k1!=k0) && (k1!=k3);
    const bool m2 = (k2!=k0) && (k2!=k3) && (k2!=k1);
    // chain head index h = max{j<=lane : !gg[j]} via shuffle max-scan
    int hh = gg ? -1 : lane;
    #pragma unroll
    for (int d = 1; d < 32; d <<= 1) {
        int hu = __shfl_up_sync(FULL, hh, d);
        if (lane >= d && hu > hh) hh = hu;
    }
    const bool h0 = (hh == 0);
    const int hm1 = (hh > 0) ? hh - 1 : 0;

    float ssum[PPT], mmax[PPT], xt[PPT];
    int amax[PPT];
    #pragma unroll
    for (int j = 0; j < PPT; j++) { ssum[j] = 0.f; mmax[j] = -1e30f; xt[j] = 0.f; amax[j] = q0; }

    const float4* base4 = reinterpret_cast<const float4*>(
        masks + (size_t)img*QN*HW + (size_t)blk*PIX);
    const int stride4 = HW/4;
    const int myf4 = w*32 + lane;

    float4 cur = base4[(size_t)q0*stride4 + myf4];    // prefetch first q
    for (int qi = 0; qi < QPG; qi++) {
        const int q = q0 + qi;
        float4 nxt;
        if (qi + 1 < QPG) nxt = base4[(size_t)(q+1)*stride4 + myf4];
        else nxt = make_float4(0.f, 0.f, 0.f, 0.f);

        float xv[PPT] = {cur.x, cur.y, cur.z, cur.w};
        float* sbuf = sig_sh[qi & 1][w];
        #pragma unroll
        for (int j = 0; j < PPT; j++) {
            float x = xv[j];
            if (x > mmax[j]) { mmax[j] = x; amax[j] = q; }
            xt[j] = (q == myc[j]) ? x : xt[j];
            float t = __expf(x);               // one exp serves both lse and sigmoid
            ssum[j] += t;
            sbuf[mypos[j]] = __fdividef(t, 1.f + t);  // sigmoid -> sorted slot
        }
        __syncwarp();                          // warp-local scatter->gather
        float4 v = reinterpret_cast<const float4*>(sbuf)[lane];

        // in-lane run merges (fixed cost, precomputed selects)
        float L = v.x + (e10 ? v.y : 0.f) + (e20 ? v.z : 0.f) + (e30 ? v.w : 0.f);
        float T = pass ? L : (v.w + (e23 ? v.z : 0.f) + (e13 ? v.y : 0.f));
        // warp prefix sum of T (unsegmented), chain sum via head base
        float x = T;
        #pragma unroll
        for (int d = 1; d < 32; d <<= 1) {
            float xu = __shfl_up_sync(FULL, x, d);
            if (lane >= d) x += xu;
        }
        float base = __shfl_sync(FULL, x, hm1);
        float S = x - (h0 ? 0.f : base);       // trail-chain sum ending at this lane
        float Sp = __shfl_up_sync(FULL, S, 1);
        float cin = conn ? Sp : 0.f;           // carry into this lane's lead run

        // plain single-writer RMW commits (class unique per run per warp)
        float* iw = &interw[w][qi*NC1];
        if (!pass)       iw[k0] += cin + L;    // lead run terminates here
        else if (term)   iw[k0] += S;          // pass-through chain terminal
        if (term && !pass) iw[k3] += T;        // trail run (starts+ends structure-safe)
        if (m1) iw[k1] += v.y + (e21 ? v.z : 0.f);
        if (m2) iw[k2] += v.z;
        cur = nxt;
        // no barrier: double buffer; next q's syncwarp orders buffer reuse
    }

    // ---- write per-pixel partials for combine_k ----
    {
        const int p4 = pixbase/4 + myf4;
        g_pssum[g][p4] = make_float4(ssum[0], ssum[1], ssum[2], ssum[3]);
        g_pmax [g][p4] = make_float4(mmax[0], mmax[1], mmax[2], mmax[3]);
        g_pxt  [g][p4] = make_float4(xt[0], xt[1], xt[2], xt[3]);
        g_pamax[g][p4] = make_uchar4((unsigned char)amax[0], (unsigned char)amax[1],
                                     (unsigned char)amax[2], (unsigned char)amax[3]);
    }
    __syncthreads();   // orders all interw writes before flush

    // ---- flush: sum 8 warp copies -> global inter + src ----
    for (int idx = tid; idx < QPG*NC1; idx += THREADS) {
        const int qi = idx / NC1;
        const int c  = idx - qi*NC1;
        float v = 0.f;
        #pragma unroll
        for (int ww = 0; ww < NWARP; ww++) v += interw[ww][idx];
        if (c < NCLS) atomicAdd(&g_inter[(img*QN + q0 + qi)*NCLS + c], v);
        atomicAdd(&src_sh[qi], v);     // src_sum includes ignore bin (c==40)
    }
    __syncthreads();
    for (int qi = tid; qi < QPG; qi += THREADS)
        atomicAdd(&g_src[img*QN + q0 + qi], src_sh[qi]);
}

// Cross-group combine: per-pixel ce_mask numerator, n_valid, assignment counts,
// and the per-image class histogram (== tsum, since Sum_q counts is q-free).
__global__ __launch_bounds__(THREADS) void combine_k(const int* __restrict__ targets)
{
    __shared__ float s_ce[NWARP];
    __shared__ float s_nv[NWARP];
    __shared__ int hist[NCLS];
    const int tid = threadIdx.x;
    const int lane = tid & 31;
    const int wid = tid >> 5;
    const int j = blockIdx.x * THREADS + tid;      // float4 pixel group
    const int img = (int)(((size_t)blockIdx.x * THREADS * 4) >> 16);

    for (int i = tid; i < NCLS; i += THREADS) hist[i] = 0;
    __syncthreads();

    float4 ssum = g_pssum[0][j];
    float4 mmax = g_pmax [0][j];
    float4 xt   = g_pxt  [0][j];
    uchar4 am   = g_pamax[0][j];
    #pragma unroll
    for (int g = 1; g < QG; g++) {
        float4 s2 = g_pssum[g][j];
        float4 m2 = g_pmax [g][j];
        float4 x2 = g_pxt  [g][j];
        uchar4 a2 = g_pamax[g][j];
        ssum.x += s2.x; ssum.y += s2.y; ssum.z += s2.z; ssum.w += s2.w;
        xt.x += x2.x; xt.y += x2.y; xt.z += x2.z; xt.w += x2.w;
        if (m2.x > mmax.x) { mmax.x = m2.x; am.x = a2.x; }
        if (m2.y > mmax.y) { mmax.y = m2.y; am.y = a2.y; }
        if (m2.z > mmax.z) { mmax.z = m2.z; am.z = a2.z; }
        if (m2.w > mmax.w) { mmax.w = m2.w; am.w = a2.w; }
    }
    int4 t4 = reinterpret_cast<const int4*>(targets)[j];

    float ce_l = 0.f, nv = 0.f;
    int tt[PPT] = {t4.x, t4.y, t4.z, t4.w};
    float ssv[PPT] = {ssum.x, ssum.y, ssum.z, ssum.w};
    float xtv[PPT] = {xt.x, xt.y, xt.z, xt.w};
    int amv[PPT] = {am.x, am.y, am.z, am.w};
    #pragma unroll
    for (int k = 0; k < PPT; k++) {
        if ((unsigned)tt[k] < (unsigned)NCLS) {
            ce_l += __logf(ssv[k]) - xtv[k];       // lse - x[target]
            nv += 1.f;
            atomicAdd(&hist[tt[k]], 1);
            atomicAdd(&g_counts[(img*QN + amv[k])*NCLS + tt[k]], 1);
        }
    }
    #pragma unroll
    for (int o = 16; o > 0; o >>= 1) {
        ce_l += __shfl_xor_sync(FULL, ce_l, o);
        nv   += __shfl_xor_sync(FULL, nv, o);
    }
    if (lane == 0) { s_ce[wid] = ce_l; s_nv[wid] = nv; }
    __syncthreads();
    if (wid == 0) {
        float c = (lane < NWARP) ? s_ce[lane] : 0.f;
        float n = (lane < NWARP) ? s_nv[lane] : 0.f;
        #pragma unroll
        for (int o = 4; o > 0; o >>= 1) {
            c += __shfl_xor_sync(FULL, c, o);
            n += __shfl_xor_sync(FULL, n, o);
        }
        if (lane == 0) { atomicAdd(&g_ce_sum, c); atomicAdd(&g_nvalid, (int)n); }
    }
    for (int c = tid; c < NCLS; c += THREADS)
        if (hist[c]) atomicAdd(&g_tsum[img*NCLS + c], hist[c]);
}

// Warp-per-(b,q) final reduction: lane-parallel mode/CE/dice; last warp finalizes.
__global__ __launch_bounds__(128) void fin_k(const float* __restrict__ logits,
                                             float* __restrict__ out)
{
    const int tid  = threadIdx.x;
    const int lane = tid & 31;
    const int item = blockIdx.x * 4 + (tid >> 5);   // (b,q), < 400
    const int b = item / QN;

    const int* cp = &g_counts[item*NCLS];
    int c1 = lane, c2 = lane + 32;
    int v1 = __ldg(cp + c1);
    int v2 = (c2 < NCLS) ? __ldg(cp + c2) : 0;
    long long kk1 = ((long long)v1 << 16) | (NCLS - c1);
    long long kk2 = (c2 < NCLS) ? (((long long)v2 << 16) | (NCLS - c2)) : 0;
    long long key = kk1 > kk2 ? kk1 : kk2;
    #pragma unroll
    for (int o = 16; o > 0; o >>= 1) {
        long long other = __shfl_xor_sync(FULL, key, o);
        if (other > key) key = other;
    }
    int bestcnt = (int)(key >> 16);
    int bestc = NCLS - (int)(key & 0xffff);

    float ce_term = 0.f;
    if (bestcnt > 0) {
        const float* lg = logits + item*NC1;
        float a = __ldg(lg + lane);
        float bb = (lane < NC1 - 32) ? __ldg(lg + lane + 32) : -1e30f;
        float m = fmaxf(a, bb);
        #pragma unroll
        for (int o = 16; o > 0; o >>= 1) m = fmaxf(m, __shfl_xor_sync(FULL, m, o));
        float s = __expf(a - m) + ((lane < NC1 - 32) ? __expf(bb - m) : 0.f);
        #pragma unroll
        for (int o = 16; o > 0; o >>= 1) s += __shfl_xor_sync(FULL, s, o);
        float lgb = __shfl_sync(FULL, (bestc < 32) ? a : bb, bestc & 31);
        float nll = m + __logf(s) - lgb;
        float p = __expf(-nll);
        float om = 1.f - p;
        ce_term = om * om * nll;
    }

    float ss = __ldg(&g_src[item]);
    float dice_l = 0.f;
    {
        float t0 = (float)__ldg(&g_tsum[0*NCLS + c1]);
        float t1 = (float)__ldg(&g_tsum[1*NCLS + c1]);
        float t2 = (float)__ldg(&g_tsum[2*NCLS + c1]);
        float t3 = (float)__ldg(&g_tsum[3*NCLS + c1]);
        float pres = (t0 + t1 + t2 + t3 > 0.f) ? 1.f : 0.f;
        float tb = (b == 0) ? t0 : (b == 1) ? t1 : (b == 2) ? t2 : t3;
        dice_l += pres * 2.f * __ldg(&g_inter[item*NCLS + c1]) / (ss + tb + 1e-8f);
        if (c2 < NCLS) {
            float u0 = (float)__ldg(&g_tsum[0*NCLS + c2]);
            float u1 = (float)__ldg(&g_tsum[1*NCLS + c2]);
            float u2 = (float)__ldg(&g_tsum[2*NCLS + c2]);
            float u3 = (float)__ldg(&g_tsum[3*NCLS + c2]);
            float pres2 = (u0 + u1 + u2 + u3 > 0.f) ? 1.f : 0.f;
            float ub = (b == 0) ? u0 : (b == 1) ? u1 : (b == 2) ? u2 : u3;
            dice_l += pres2 * 2.f * __ldg(&g_inter[item*NCLS + c2]) / (ss + ub + 1e-8f);
        }
    }
    #pragma unroll
    for (int o = 16; o > 0; o >>= 1) dice_l += __shfl_xor_sync(FULL, dice_l, o);

    bool last = false;
    if (lane == 0) {
        atomicAdd(&g_ce2, ce_term);
        atomicAdd(&g_dice2, dice_l);
        __threadfence();
        last = (atomicAdd(&g_done, 1) == FIN_WARPS - 1);
    }
    if (__shfl_sync(FULL, last ? 1 : 0, 0)) {
        float pr = 0.f;
        if (lane < NCLS) {
            int t = __ldg(&g_tsum[0*NCLS + lane]) + __ldg(&g_tsum[1*NCLS + lane])
                  + __ldg(&g_tsum[2*NCLS + lane]) + __ldg(&g_tsum[3*NCLS + lane]);
            pr = (t > 0) ? 1.f : 0.f;
        }
        float pr2 = 0.f;
        if (lane + 32 < NCLS) {
            int t = __ldg(&g_tsum[0*NCLS + lane+32]) + __ldg(&g_tsum[1*NCLS + lane+32])
                  + __ldg(&g_tsum[2*NCLS + lane+32]) + __ldg(&g_tsum[3*NCLS + lane+32]);
            pr2 = (t > 0) ? 1.f : 0.f;
        }
        float npres = pr + pr2;
        #pragma unroll
        for (int o = 16; o > 0; o >>= 1) npres += __shfl_xor_sync(FULL, npres, o);
        if (lane == 0) {
            float ce_tot   = *(volatile float*)&g_ce2;
            float dice_tot = *(volatile float*)&g_dice2;
            float loss_ce = ce_tot / (float)(BN*QN);
            float ce_mask = g_ce_sum / fmaxf((float)g_nvalid, 1.f);
            float dice_loss = (npres - dice_tot / (float)(BN*QN)) / (float)NCLS;
            out[0] = 2.f*loss_ce + 5.f*ce_mask + 5.f*dice_loss;
        }
    }
}

extern "C" void kernel_launch(void* const* d_in, const int* in_sizes, int n_in,
                              void* d_out, int out_size)
{
    const float* logits  = (const float*)d_in[0];   // [4,100,41] f32
    const float* masks   = (const float*)d_in[1];   // [4,100,256,256] f32
    const int*   targets = (const int*)d_in[2];     // [4,256,256] i32
    float* out = (float*)d_out;

    zero_k<<<(BN*QN*NCLS + 255)/256, 256>>>();
    main_k<<<NBLK_MAIN, THREADS>>>(masks, targets);
    combine_k<<<NPIX/4/THREADS, THREADS>>>(targets);
    fin_k<<<FIN_BLOCKS, 128>>>(logits, out);
}